// round 1
// baseline (speedup 1.0000x reference)
#include <cuda_runtime.h>

#define NN 4096
#define SPLIT 16

__device__ __forceinline__ float ex2_approx(float x) {
    float r;
    asm("ex2.approx.ftz.f32 %0, %1;" : "=f"(r) : "f"(x));
    return r;
}

// Constants from the reference
#define PED_SPEED   1.5f
#define ROBOT_SPEED 1.5f
#define K_ATTR      2.0f
#define ALPHA       10.0f
#define PED_RADIUS  0.3f
#define PED_MASS    60.0f
#define BETTA       0.71f
#define DT          0.4f
#define A_COST      4.0f
#define B_COST      1.2f
#define E_COST      0.001f
#define EPSF        1e-8f
#define LOG2E       1.4426950408889634f

// Kernel 1: N^2 repulsion + attraction + pose propagation.
// 16 threads per row; each block handles 16 rows, caches all positions in smem.
__global__ void __launch_bounds__(256) forces_kernel(
    const float4* __restrict__ state,   // (N,4): x,y,vx,vy
    const float2* __restrict__ goals,   // (N,2)
    float4* __restrict__ out_state)     // (N,4)
{
    __shared__ float2 spos[NN];
    const int tid = threadIdx.x;

    // Cache all positions (32 KB)
    #pragma unroll 4
    for (int j = tid; j < NN; j += 256) {
        float4 s = state[j];
        spos[j] = make_float2(s.x, s.y);
    }
    __syncthreads();

    const int row  = blockIdx.x * (256 / SPLIT) + (tid >> 4);
    const int lane = tid & (SPLIT - 1);
    const float2 p = spos[row];

    // mag = ALPHA * exp((2R - d)/BETTA) = ALPHA * 2^(C0 + C1*d)
    const float C1 = -LOG2E / BETTA;
    const float C0 = (2.0f * PED_RADIUS) * LOG2E / BETTA;

    float fx = 0.0f, fy = 0.0f;
    #pragma unroll 4
    for (int j = lane; j < NN; j += SPLIT) {
        float2 q  = spos[j];
        float dx  = p.x - q.x;
        float dy  = p.y - q.y;
        float s2  = fmaf(dx, dx, fmaf(dy, dy, EPSF));
        float rin = rsqrtf(s2);
        float d   = s2 * rin;                   // = sqrt(s2)
        float m   = ex2_approx(fmaf(d, C1, C0));
        float f   = (j == row) ? 0.0f : m * rin; // mag/d factor (ALPHA folded later)
        fx = fmaf(f, dx, fx);
        fy = fmaf(f, dy, fy);
    }

    // Reduce across the 16 lanes of this row
    #pragma unroll
    for (int m = SPLIT / 2; m > 0; m >>= 1) {
        fx += __shfl_xor_sync(0xffffffffu, fx, m);
        fy += __shfl_xor_sync(0xffffffffu, fy, m);
    }

    if (lane == 0) {
        fx *= ALPHA;
        fy *= ALPHA;

        float4 st = state[row];
        float2 g  = goals[row];
        float tgx = g.x - st.x;
        float tgy = g.y - st.y;
        float dist = sqrtf(fmaf(tgx, tgx, tgy * tgy));
        float einv = 1.0f / (dist + EPSF);
        float ds   = (row == 0) ? ROBOT_SPEED : PED_SPEED;
        // attr = K*(ds*e_goal - vel)*MASS
        float ax = K_ATTR * (ds * tgx * einv - st.z) * PED_MASS;
        float ay = K_ATTR * (ds * tgy * einv - st.w) * PED_MASS;

        float Fx = fx + ax;
        float Fy = fy + ay;

        // vel_new = vel + F/MASS*DT, clamped to PED_SPEED
        float vnx = fmaf(Fx, DT / PED_MASS, st.z);
        float vny = fmaf(Fy, DT / PED_MASS, st.w);
        float speed = sqrtf(fmaf(vnx, vnx, vny * vny));
        float sc = fminf(1.0f, PED_SPEED / (speed + EPSF));
        vnx *= sc;
        vny *= sc;

        out_state[row] = make_float4(fmaf(vnx, DT, st.x),
                                     fmaf(vny, DT, st.y),
                                     vnx, vny);
    }
}

// Kernel 2: cost (needs robot pose = out_state[0]) + stacked-output copy.
__global__ void __launch_bounds__(256) cost_kernel(
    const float4* __restrict__ state,
    const float4* __restrict__ stacked_in,
    const float*  __restrict__ cost_in,
    const float2* __restrict__ goals,
    const float*  __restrict__ robot_init,
    const float4* __restrict__ out_state,
    float* __restrict__ out_cost,
    float4* __restrict__ out_stacked)
{
    int i = blockIdx.x * blockDim.x + threadIdx.x;
    if (i >= NN) return;

    float4 r0 = out_state[0];
    float rix = robot_init[0];
    float riy = robot_init[1];
    float gx  = goals[0].x - rix;
    float gy  = goals[0].y - riy;
    float PG  = (gx * (r0.x - rix) + gy * (r0.y - riy)) /
                (sqrtf(fmaf(gx, gx, gy * gy)) + E_COST);

    float4 s  = out_state[i];
    float ddx = s.x - r0.x;
    float ddy = s.y - r0.y;
    float dr  = sqrtf(fmaf(ddx, ddx, fmaf(ddy, ddy, E_COST)));
    float blame = (i == 0) ? 0.0f : ex2_approx(-dr * (LOG2E / B_COST));

    out_cost[i] = cost_in[i] + (-A_COST * PG + blame);

    // stacked = concat(stacked_in, state)
    out_stacked[i]      = stacked_in[i];
    out_stacked[NN + i] = state[i];
}

extern "C" void kernel_launch(void* const* d_in, const int* in_sizes, int n_in,
                              void* d_out, int out_size)
{
    const float4* state   = (const float4*)d_in[0];
    const float*  cost    = (const float*)d_in[1];
    const float4* stacked = (const float4*)d_in[2];
    const float2* goals   = (const float2*)d_in[3];
    const float*  rinit   = (const float*)d_in[4];

    float* out = (float*)d_out;
    float4* out_state   = (float4*)out;                 // [0, 4N)
    float*  out_cost    = out + 4 * NN;                 // [4N, 5N)
    float4* out_stacked = (float4*)(out + 5 * NN);      // [5N, 13N)

    forces_kernel<<<NN / (256 / SPLIT), 256>>>(state, goals, out_state);
    cost_kernel<<<(NN + 255) / 256, 256>>>(state, stacked, cost, goals, rinit,
                                           out_state, out_cost, out_stacked);
}

// round 2
// speedup vs baseline: 1.0122x; 1.0122x over previous
#include <cuda_runtime.h>

#define NN 4096
#define SPLIT 16

__device__ __forceinline__ float ex2_approx(float x) {
    float r;
    asm("ex2.approx.ftz.f32 %0, %1;" : "=f"(r) : "f"(x));
    return r;
}

// Constants from the reference
#define PED_SPEED   1.5f
#define ROBOT_SPEED 1.5f
#define K_ATTR      2.0f
#define ALPHA       10.0f
#define PED_RADIUS  0.3f
#define PED_MASS    60.0f
#define BETTA       0.71f
#define DT          0.4f
#define A_COST      4.0f
#define B_COST      1.2f
#define E_COST      0.001f
#define EPSF        1e-8f
#define LOG2E       1.4426950408889634f

// Kernel 1: N^2 repulsion + attraction + pose propagation.
// 16 threads per row; each block handles 16 rows, caches all positions in smem.
__global__ void __launch_bounds__(256) forces_kernel(
    const float4* __restrict__ state,   // (N,4): x,y,vx,vy
    const float2* __restrict__ goals,   // (N,2)
    float4* __restrict__ out_state)     // (N,4)
{
    __shared__ float2 spos[NN];
    const int tid = threadIdx.x;

    // Cache all positions (32 KB)
    #pragma unroll 4
    for (int j = tid; j < NN; j += 256) {
        float4 s = state[j];
        spos[j] = make_float2(s.x, s.y);
    }
    __syncthreads();

    const int row  = blockIdx.x * (256 / SPLIT) + (tid >> 4);
    const int lane = tid & (SPLIT - 1);
    const float2 p = spos[row];

    // mag = ALPHA * exp((2R - d)/BETTA) = ALPHA * 2^(C0 + C1*d)
    const float C1 = -LOG2E / BETTA;
    const float C0 = (2.0f * PED_RADIUS) * LOG2E / BETTA;

    float fx = 0.0f, fy = 0.0f;
    #pragma unroll 4
    for (int j = lane; j < NN; j += SPLIT) {
        float2 q  = spos[j];
        float dx  = p.x - q.x;
        float dy  = p.y - q.y;
        float s2  = fmaf(dx, dx, fmaf(dy, dy, EPSF));
        float rin = rsqrtf(s2);
        float d   = s2 * rin;                   // = sqrt(s2)
        float m   = ex2_approx(fmaf(d, C1, C0));
        float f   = (j == row) ? 0.0f : m * rin; // mag/d factor (ALPHA folded later)
        fx = fmaf(f, dx, fx);
        fy = fmaf(f, dy, fy);
    }

    // Reduce across the 16 lanes of this row
    #pragma unroll
    for (int m = SPLIT / 2; m > 0; m >>= 1) {
        fx += __shfl_xor_sync(0xffffffffu, fx, m);
        fy += __shfl_xor_sync(0xffffffffu, fy, m);
    }

    if (lane == 0) {
        fx *= ALPHA;
        fy *= ALPHA;

        float4 st = state[row];
        float2 g  = goals[row];
        float tgx = g.x - st.x;
        float tgy = g.y - st.y;
        float dist = sqrtf(fmaf(tgx, tgx, tgy * tgy));
        float einv = 1.0f / (dist + EPSF);
        float ds   = (row == 0) ? ROBOT_SPEED : PED_SPEED;
        // attr = K*(ds*e_goal - vel)*MASS
        float ax = K_ATTR * (ds * tgx * einv - st.z) * PED_MASS;
        float ay = K_ATTR * (ds * tgy * einv - st.w) * PED_MASS;

        float Fx = fx + ax;
        float Fy = fy + ay;

        // vel_new = vel + F/MASS*DT, clamped to PED_SPEED
        float vnx = fmaf(Fx, DT / PED_MASS, st.z);
        float vny = fmaf(Fy, DT / PED_MASS, st.w);
        float speed = sqrtf(fmaf(vnx, vnx, vny * vny));
        float sc = fminf(1.0f, PED_SPEED / (speed + EPSF));
        vnx *= sc;
        vny *= sc;

        out_state[row] = make_float4(fmaf(vnx, DT, st.x),
                                     fmaf(vny, DT, st.y),
                                     vnx, vny);
    }
}

// Kernel 2: cost (needs robot pose = out_state[0]) + stacked-output copy.
__global__ void __launch_bounds__(256) cost_kernel(
    const float4* __restrict__ state,
    const float4* __restrict__ stacked_in,
    const float*  __restrict__ cost_in,
    const float2* __restrict__ goals,
    const float*  __restrict__ robot_init,
    const float4* __restrict__ out_state,
    float* __restrict__ out_cost,
    float4* __restrict__ out_stacked)
{
    int i = blockIdx.x * blockDim.x + threadIdx.x;
    if (i >= NN) return;

    float4 r0 = out_state[0];
    float rix = robot_init[0];
    float riy = robot_init[1];
    float gx  = goals[0].x - rix;
    float gy  = goals[0].y - riy;
    float PG  = (gx * (r0.x - rix) + gy * (r0.y - riy)) /
                (sqrtf(fmaf(gx, gx, gy * gy)) + E_COST);

    float4 s  = out_state[i];
    float ddx = s.x - r0.x;
    float ddy = s.y - r0.y;
    float dr  = sqrtf(fmaf(ddx, ddx, fmaf(ddy, ddy, E_COST)));
    float blame = (i == 0) ? 0.0f : ex2_approx(-dr * (LOG2E / B_COST));

    out_cost[i] = cost_in[i] + (-A_COST * PG + blame);

    // stacked = concat(stacked_in, state)
    out_stacked[i]      = stacked_in[i];
    out_stacked[NN + i] = state[i];
}

extern "C" void kernel_launch(void* const* d_in, const int* in_sizes, int n_in,
                              void* d_out, int out_size)
{
    const float4* state   = (const float4*)d_in[0];
    const float*  cost    = (const float*)d_in[1];
    const float4* stacked = (const float4*)d_in[2];
    const float2* goals   = (const float2*)d_in[3];
    const float*  rinit   = (const float*)d_in[4];

    float* out = (float*)d_out;
    float4* out_state   = (float4*)out;                 // [0, 4N)
    float*  out_cost    = out + 4 * NN;                 // [4N, 5N)
    float4* out_stacked = (float4*)(out + 5 * NN);      // [5N, 13N)

    forces_kernel<<<NN / (256 / SPLIT), 256>>>(state, goals, out_state);
    cost_kernel<<<(NN + 255) / 256, 256>>>(state, stacked, cost, goals, rinit,
                                           out_state, out_cost, out_stacked);
}

// round 3
// speedup vs baseline: 1.2388x; 1.2239x over previous
#include <cuda_runtime.h>

#define NN    4096
#define SPLIT 16
#define TPB   256
#define RPB   (TPB / SPLIT)   // rows per block = 16

#define PED_SPEED   1.5f
#define ROBOT_SPEED 1.5f
#define K_ATTR      2.0f
#define ALPHA       10.0f
#define PED_RADIUS  0.3f
#define PED_MASS    60.0f
#define BETTA       0.71f
#define DT          0.4f
#define A_COST      4.0f
#define B_COST      1.2f
#define E_COST      0.001f
#define EPSF        1e-8f
#define LOG2E       1.4426950408889634f

__device__ __forceinline__ float ex2_approx(float x) {
    float r;
    asm("ex2.approx.ftz.f32 %0, %1;" : "=f"(r) : "f"(x));
    return r;
}

// One fused kernel: N^2 forces + pose propagation + redundant row-0 pose per
// block (for the cost term) + cost + stacked copy. 256 blocks x 256 threads,
// 16 lanes cooperate per row. Inner loop uses packed f32x2 PTX (sm_103a).
__global__ void __launch_bounds__(256) fused_kernel(
    const float4* __restrict__ state,      // (N,4): x,y,vx,vy
    const float*  __restrict__ cost_in,    // (N)
    const float4* __restrict__ stacked_in, // (N,4)
    const float2* __restrict__ goals,      // (N,2)
    const float*  __restrict__ robot_init, // (2)
    float4* __restrict__ out_state,
    float*  __restrict__ out_cost,
    float4* __restrict__ out_stacked)
{
    __shared__ float2 sneg[NN];          // negated positions (32 KB)
    __shared__ float2 wsum[TPB / 32];    // row-0 block reduction
    __shared__ float  robo[3];           // r0x, r0y, PG

    const int tid = threadIdx.x;
    const int b   = blockIdx.x;

    // Stacked output copy for this block's 16 rows (2 x 16 float4)
    if (tid < RPB) {
        int r = b * RPB + tid;
        out_stacked[r] = stacked_in[r];
    } else if (tid < 2 * RPB) {
        int r = b * RPB + (tid - RPB);
        out_stacked[NN + r] = state[r];
    }

    // Cache NEGATED positions so diff = p + (-q) is one packed add
    #pragma unroll 4
    for (int j = tid; j < NN; j += TPB) {
        float4 s = state[j];
        sneg[j] = make_float2(-s.x, -s.y);
    }
    __syncthreads();

    const int row  = b * RPB + (tid >> 4);
    const int lane = tid & (SPLIT - 1);

    const float4 st = state[row];  // 16 lanes same addr -> broadcast, L1/L2 hit

    const float C1 = -LOG2E / BETTA;
    const float C0 = (2.0f * PED_RADIUS) * LOG2E / BETTA;

    unsigned long long p64, acc;
    asm("mov.b64 %0, {%1,%2};" : "=l"(p64) : "f"(st.x), "f"(st.y));
    asm("mov.b64 %0, {%1,%1};" : "=l"(acc) : "f"(0.0f));

    const unsigned long long* __restrict__ sq =
        reinterpret_cast<const unsigned long long*>(sneg);

    // Main N^2 loop. Self-pair (j==row) contributes exactly 0 because
    // dx=dy=0 and f stays finite (EPS inside the sqrt) -> no mask needed.
    #pragma unroll 8
    for (int j = lane; j < NN; j += SPLIT) {
        unsigned long long q64 = sq[j];                 // LDS.64, conflict-free
        unsigned long long diff, f2;
        float dx, dy;
        asm("add.rn.f32x2 %0, %1, %2;" : "=l"(diff) : "l"(p64), "l"(q64));
        asm("mov.b64 {%0,%1}, %2;" : "=f"(dx), "=f"(dy) : "l"(diff));
        float s2  = fmaf(dx, dx, fmaf(dy, dy, EPSF));
        float rin = rsqrtf(s2);
        float d   = s2 * rin;
        float m   = ex2_approx(fmaf(d, C1, C0));
        float f   = m * rin;
        asm("mov.b64 %0, {%1,%1};" : "=l"(f2) : "f"(f));
        asm("fma.rn.f32x2 %0, %1, %2, %3;" : "=l"(acc) : "l"(f2), "l"(diff), "l"(acc));
    }

    float fx, fy;
    asm("mov.b64 {%0,%1}, %2;" : "=f"(fx), "=f"(fy) : "l"(acc));
    #pragma unroll
    for (int sh = SPLIT / 2; sh > 0; sh >>= 1) {
        fx += __shfl_xor_sync(0xffffffffu, fx, sh);
        fy += __shfl_xor_sync(0xffffffffu, fy, sh);
    }

    // Lane 0: attraction + pose propagation for own row
    float pnx = 0.0f, pny = 0.0f;
    if (lane == 0) {
        fx *= ALPHA;
        fy *= ALPHA;

        float2 g   = goals[row];
        float tgx  = g.x - st.x;
        float tgy  = g.y - st.y;
        float dist = sqrtf(fmaf(tgx, tgx, tgy * tgy));
        float einv = 1.0f / (dist + EPSF);
        float ds   = (row == 0) ? ROBOT_SPEED : PED_SPEED;
        float Fx   = fx + K_ATTR * (ds * tgx * einv - st.z) * PED_MASS;
        float Fy   = fy + K_ATTR * (ds * tgy * einv - st.w) * PED_MASS;

        float vnx   = fmaf(Fx, DT / PED_MASS, st.z);
        float vny   = fmaf(Fy, DT / PED_MASS, st.w);
        float speed = sqrtf(fmaf(vnx, vnx, vny * vny));
        float sc    = fminf(1.0f, PED_SPEED / (speed + EPSF));
        vnx *= sc;
        vny *= sc;
        pnx = fmaf(vnx, DT, st.x);
        pny = fmaf(vny, DT, st.y);
        out_state[row] = make_float4(pnx, pny, vnx, vny);
    }

    // ---- Redundant row-0 force (every block; 16 iters/thread = +6% work) ----
    const float4 s0 = state[0];
    float f0x = 0.0f, f0y = 0.0f;
    #pragma unroll
    for (int k = 0; k < NN / TPB; k++) {
        float2 nq = sneg[tid + k * TPB];
        float dx  = s0.x + nq.x;
        float dy  = s0.y + nq.y;
        float s2  = fmaf(dx, dx, fmaf(dy, dy, EPSF));
        float rin = rsqrtf(s2);
        float d   = s2 * rin;
        float mm  = ex2_approx(fmaf(d, C1, C0));
        float f   = mm * rin;
        f0x = fmaf(f, dx, f0x);
        f0y = fmaf(f, dy, f0y);
    }
    #pragma unroll
    for (int sh = 16; sh > 0; sh >>= 1) {
        f0x += __shfl_xor_sync(0xffffffffu, f0x, sh);
        f0y += __shfl_xor_sync(0xffffffffu, f0y, sh);
    }
    if ((tid & 31) == 0) wsum[tid >> 5] = make_float2(f0x, f0y);
    __syncthreads();

    if (tid == 0) {
        float rx = 0.0f, ry = 0.0f;
        #pragma unroll
        for (int w = 0; w < TPB / 32; w++) { rx += wsum[w].x; ry += wsum[w].y; }
        rx *= ALPHA;
        ry *= ALPHA;

        float2 g0  = goals[0];
        float tgx  = g0.x - s0.x;
        float tgy  = g0.y - s0.y;
        float dist = sqrtf(fmaf(tgx, tgx, tgy * tgy));
        float einv = 1.0f / (dist + EPSF);
        float Fx   = rx + K_ATTR * (ROBOT_SPEED * tgx * einv - s0.z) * PED_MASS;
        float Fy   = ry + K_ATTR * (ROBOT_SPEED * tgy * einv - s0.w) * PED_MASS;

        float vnx   = fmaf(Fx, DT / PED_MASS, s0.z);
        float vny   = fmaf(Fy, DT / PED_MASS, s0.w);
        float speed = sqrtf(fmaf(vnx, vnx, vny * vny));
        float sc    = fminf(1.0f, PED_SPEED / (speed + EPSF));
        vnx *= sc;
        vny *= sc;
        float r0x = fmaf(vnx, DT, s0.x);
        float r0y = fmaf(vny, DT, s0.y);

        float rix = robot_init[0];
        float riy = robot_init[1];
        float gx  = g0.x - rix;
        float gy  = g0.y - riy;
        float PG  = (gx * (r0x - rix) + gy * (r0y - riy)) /
                    (sqrtf(fmaf(gx, gx, gy * gy)) + E_COST);
        robo[0] = r0x;
        robo[1] = r0y;
        robo[2] = PG;
    }
    __syncthreads();

    // Lane 0: cost for own row
    if (lane == 0) {
        float r0x = robo[0], r0y = robo[1], PG = robo[2];
        float ddx = pnx - r0x;
        float ddy = pny - r0y;
        float dr  = sqrtf(fmaf(ddx, ddx, fmaf(ddy, ddy, E_COST)));
        float blame = (row == 0) ? 0.0f : ex2_approx(-dr * (LOG2E / B_COST));
        out_cost[row] = cost_in[row] + (-A_COST * PG + blame);
    }
}

extern "C" void kernel_launch(void* const* d_in, const int* in_sizes, int n_in,
                              void* d_out, int out_size)
{
    const float4* state   = (const float4*)d_in[0];
    const float*  cost    = (const float*)d_in[1];
    const float4* stacked = (const float4*)d_in[2];
    const float2* goals   = (const float2*)d_in[3];
    const float*  rinit   = (const float*)d_in[4];

    float*  out         = (float*)d_out;
    float4* out_state   = (float4*)out;            // [0, 4N)
    float*  out_cost    = out + 4 * NN;            // [4N, 5N)
    float4* out_stacked = (float4*)(out + 5 * NN); // [5N, 13N)

    fused_kernel<<<NN / RPB, TPB>>>(state, cost, stacked, goals, rinit,
                                    out_state, out_cost, out_stacked);
}